// round 17
// baseline (speedup 1.0000x reference)
#include <cuda_runtime.h>
#include <cuda_bf16.h>

// JPEG q=99 luma-only path (chroma provably constant for grayscale-replicated input).
// Thread-per-8x8-tile, warp-autonomous (R15 structure) + packed f32x2 transforms:
// row passes packed over row pairs, column passes packed over column pairs.

#define C1f 0.98078528040323044913f
#define C2f 0.92387953251128675613f
#define C3f 0.83146961230254523708f
#define C4f 0.70710678118654752440f
#define C5f 0.55557023301960222474f
#define C6f 0.38268343236508977173f
#define C7f 0.19509032201612826785f

typedef unsigned long long u64p;

__device__ __forceinline__ u64p pk2(float l, float h) {
    u64p r;
    asm("mov.b64 %0, {%1, %2};" : "=l"(r) : "r"(__float_as_uint(l)), "r"(__float_as_uint(h)));
    return r;
}
__device__ __forceinline__ float lo2(u64p v) { return __uint_as_float((unsigned)v); }
__device__ __forceinline__ float hi2(u64p v) { return __uint_as_float((unsigned)(v >> 32)); }
__device__ __forceinline__ u64p add2(u64p a, u64p b) {
    u64p d; asm("add.rn.f32x2 %0, %1, %2;" : "=l"(d) : "l"(a), "l"(b)); return d;
}
__device__ __forceinline__ u64p sub2(u64p a, u64p b) {
    u64p d; asm("sub.rn.f32x2 %0, %1, %2;" : "=l"(d) : "l"(a), "l"(b)); return d;
}
__device__ __forceinline__ u64p mul2(u64p a, u64p b) {
    u64p d; asm("mul.rn.f32x2 %0, %1, %2;" : "=l"(d) : "l"(a), "l"(b)); return d;
}
__device__ __forceinline__ u64p fma2p(u64p a, u64p b, u64p c) {
    u64p d; asm("fma.rn.f32x2 %0, %1, %2, %3;" : "=l"(d) : "l"(a), "l"(b), "l"(c)); return d;
}

struct PC {   // packed DCT constants (each half identical)
    u64p c1, c2, c3, c4, c5, c6, c7;
};

__device__ __forceinline__ void dct8p(const u64p in[8], u64p out[8], const PC& K) {
    u64p s0 = add2(in[0], in[7]), s1 = add2(in[1], in[6]);
    u64p s2 = add2(in[2], in[5]), s3 = add2(in[3], in[4]);
    u64p d0 = sub2(in[0], in[7]), d1 = sub2(in[1], in[6]);
    u64p d2 = sub2(in[2], in[5]), d3 = sub2(in[3], in[4]);
    u64p u0 = add2(s0, s3), u1 = add2(s1, s2);
    u64p t0 = sub2(s0, s3), t1 = sub2(s1, s2);
    out[0] = add2(u0, u1);
    out[4] = mul2(K.c4, sub2(u0, u1));
    out[2] = fma2p(K.c2, t0, mul2(K.c6, t1));
    out[6] = sub2(mul2(K.c6, t0), mul2(K.c2, t1));
    out[1] = fma2p(K.c1, d0, fma2p(K.c3, d1, fma2p(K.c5, d2, mul2(K.c7, d3))));
    out[3] = sub2(mul2(K.c3, d0), fma2p(K.c7, d1, fma2p(K.c1, d2, mul2(K.c5, d3))));
    out[5] = sub2(fma2p(K.c5, d0, fma2p(K.c7, d2, mul2(K.c3, d3))), mul2(K.c1, d1));
    out[7] = sub2(fma2p(K.c7, d0, mul2(K.c3, d2)), fma2p(K.c5, d1, mul2(K.c1, d3)));
}

__device__ __forceinline__ void idct8p(const u64p e[8], u64p out[8], const PC& K) {
    u64p ev0 = fma2p(K.c2, e[2], fma2p(K.c4, e[4], fma2p(K.c6, e[6], e[0])));
    u64p ev1 = sub2(fma2p(K.c6, e[2], e[0]), fma2p(K.c4, e[4], mul2(K.c2, e[6])));
    u64p ev2 = sub2(fma2p(K.c2, e[6], e[0]), fma2p(K.c6, e[2], mul2(K.c4, e[4])));
    u64p ev3 = sub2(fma2p(K.c4, e[4], e[0]), fma2p(K.c2, e[2], mul2(K.c6, e[6])));
    u64p od0 = fma2p(K.c1, e[1], fma2p(K.c3, e[3], fma2p(K.c5, e[5], mul2(K.c7, e[7]))));
    u64p od1 = sub2(mul2(K.c3, e[1]), fma2p(K.c7, e[3], fma2p(K.c1, e[5], mul2(K.c5, e[7]))));
    u64p od2 = sub2(fma2p(K.c5, e[1], fma2p(K.c7, e[5], mul2(K.c3, e[7]))), mul2(K.c1, e[3]));
    u64p od3 = sub2(fma2p(K.c7, e[1], mul2(K.c3, e[5])), fma2p(K.c5, e[3], mul2(K.c1, e[7])));
    out[0] = add2(ev0, od0);  out[7] = sub2(ev0, od0);
    out[1] = add2(ev1, od1);  out[6] = sub2(ev1, od1);
    out[2] = add2(ev2, od2);  out[5] = sub2(ev2, od2);
    out[3] = add2(ev3, od3);  out[4] = sub2(ev3, od3);
}

#define CH_STRIDE 197     // ODD: bank-conflict-free window reads/writes
#define WARPS_BLK 4

__global__ __launch_bounds__(128, 4)
void jpeg_y_kernel(const float* __restrict__ x, float* __restrict__ out, int nch)
{
    constexpr float YQT[64] = {
        16.f, 11.f, 10.f, 16.f, 24.f, 40.f, 51.f, 61.f,
        12.f, 12.f, 14.f, 19.f, 26.f, 58.f, 60.f, 55.f,
        14.f, 13.f, 16.f, 24.f, 40.f, 57.f, 69.f, 56.f,
        14.f, 17.f, 22.f, 29.f, 51.f, 87.f, 80.f, 62.f,
        18.f, 22.f, 37.f, 56.f, 68.f,109.f,103.f, 77.f,
        24.f, 35.f, 55.f, 64.f, 81.f,104.f,113.f, 92.f,
        49.f, 64.f, 78.f, 87.f,103.f,121.f,120.f,101.f,
        72.f, 92.f, 95.f, 98.f,112.f,100.f,103.f, 99.f
    };
    constexpr float AL[8] = { C4f, 1.f, 1.f, 1.f, 1.f, 1.f, 1.f, 1.f };

    __shared__ float shd[WARPS_BLK * 8 * CH_STRIDE];   // 24.6 KB

    const int lane = threadIdx.x & 31;
    const int wrp  = threadIdx.x >> 5;
    const int chs  = lane >> 2;
    const int q    = lane & 3;           // quarter for staging; tile for compute
    const int br   = q >> 1, bc = q & 1;
    const int gch  = (blockIdx.x * WARPS_BLK + wrp) * 8 + chs;
    const bool act = gch < nch;
    float* cb = shd + (wrp * 8 + chs) * CH_STRIDE;

    PC K;
    K.c1 = pk2(C1f, C1f); K.c2 = pk2(C2f, C2f); K.c3 = pk2(C3f, C3f);
    K.c4 = pk2(C4f, C4f); K.c5 = pk2(C5f, C5f); K.c6 = pk2(C6f, C6f);
    K.c7 = pk2(C7f, C7f);

    // ---- stage own channel quarter (LDG.128 -> scalar STS) + min/max fold ----
    float mn = 3.4e38f, mx = -3.4e38f;
    if (act) {
        const float4* xg4 = (const float4*)(x + (size_t)gch * 196);
        #pragma unroll
        for (int k = 0; k < 13; k++) {
            int i = q + 4 * k;
            if (i < 49) {
                float4 v = xg4[i];
                cb[4*i+0] = v.x; cb[4*i+1] = v.y; cb[4*i+2] = v.z; cb[4*i+3] = v.w;
                mn = fminf(mn, fminf(fminf(v.x, v.y), fminf(v.z, v.w)));
                mx = fmaxf(mx, fmaxf(fmaxf(v.x, v.y), fmaxf(v.z, v.w)));
            }
        }
    }
    __syncwarp();

    mn = fminf(mn, __shfl_xor_sync(0xffffffffu, mn, 1));
    mx = fmaxf(mx, __shfl_xor_sync(0xffffffffu, mx, 1));
    mn = fminf(mn, __shfl_xor_sync(0xffffffffu, mn, 2));
    mx = fmaxf(mx, __shfl_xor_sync(0xffffffffu, mx, 2));
    const float rng = mx - mn + 1e-5f;
    const float sc  = 255.0f / rng;
    const float off = -mn * sc - 128.0f;     // w = raw*sc + off
    const u64p scp  = pk2(sc, sc);
    const u64p offp = pk2(off, off);

    float A[64];

    // ---- pass 1: row DCT packed over row pairs ----
    #pragma unroll
    for (int xp = 0; xp < 4; xp++) {
        int rA = min(max(8 * br + 2 * xp - 1, 0), 13);
        int rB = min(max(8 * br + 2 * xp    , 0), 13);
        u64p w[8], r[8];
        #pragma unroll
        for (int y = 0; y < 8; y++) {
            int col = min(max(8 * bc + y - 1, 0), 13);
            w[y] = fma2p(pk2(cb[rA * 14 + col], cb[rB * 14 + col]), scp, offp);
        }
        dct8p(w, r, K);
        #pragma unroll
        for (int v = 0; v < 8; v++) {
            A[(2 * xp)     * 8 + v] = lo2(r[v]);
            A[(2 * xp + 1) * 8 + v] = hi2(r[v]);
        }
    }

    // ---- pass 2+3: column DCT + quant + column IDCT, packed over column pairs ----
    #pragma unroll
    for (int vp = 0; vp < 4; vp++) {
        u64p h[8], d[8], e[8], s[8];
        #pragma unroll
        for (int xr = 0; xr < 8; xr++)
            h[xr] = pk2(A[xr * 8 + 2 * vp], A[xr * 8 + 2 * vp + 1]);
        dct8p(h, d, K);
        #pragma unroll
        for (int u = 0; u < 8; u++) {
            const int vA = 2 * vp, vB = 2 * vp + 1;
            const float aaA = AL[u] * AL[vA], aaB = AL[u] * AL[vB];
            const float qsA = YQT[u * 8 + vA] * 0.02f, qsB = YQT[u * 8 + vB] * 0.02f;
            const float iqA = 0.25f * aaA / qsA, iqB = 0.25f * aaB / qsB;  // literals
            const float dqA = qsA * aaA,          dqB = qsB * aaB;          // literals
            float qdA = lo2(d[u]) * iqA;
            float qdB = hi2(d[u]) * iqB;
            float rA = rintf(qdA), rB = rintf(qdB);     // round-half-even == jnp.round
            float dA = qdA - rA,   dB = qdB - rB;
            float eA = fmaf(dA * dA, dA, rA) * dqA;
            float eB = fmaf(dB * dB, dB, rB) * dqB;
            e[u] = pk2(eA, eB);
        }
        idct8p(e, s, K);
        #pragma unroll
        for (int xr = 0; xr < 8; xr++) {
            A[xr * 8 + 2 * vp]     = lo2(s[xr]);
            A[xr * 8 + 2 * vp + 1] = hi2(s[xr]);
        }
    }

    __syncwarp();    // all window reads complete before output overwrites buffer

    // ---- pass 4: row IDCT packed over row pairs + crop/clip/denorm -> shared ----
    {
        const float dsc = rng * (1.0f / 255.0f);
        #pragma unroll
        for (int xp = 0; xp < 4; xp++) {
            u64p e2[8], p2[8];
            #pragma unroll
            for (int v = 0; v < 8; v++)
                e2[v] = pk2(A[(2 * xp) * 8 + v], A[(2 * xp + 1) * 8 + v]);
            idct8p(e2, p2, K);
            const int iA = 8 * br + 2 * xp - 1;
            const int iB = iA + 1;
            #pragma unroll
            for (int y = 0; y < 8; y++) {
                int j = 8 * bc + y - 1;
                if ((unsigned)j < 14u) {
                    if ((unsigned)iA < 14u) {
                        float pv = fmaf(0.25f, lo2(p2[y]), 128.0f);
                        pv = fminf(fmaxf(pv, 0.0f), 255.0f);
                        cb[iA * 14 + j] = fmaf(pv, dsc, mn);
                    }
                    if ((unsigned)iB < 14u) {
                        float pv = fmaf(0.25f, hi2(p2[y]), 128.0f);
                        pv = fminf(fmaxf(pv, 0.0f), 255.0f);
                        cb[iB * 14 + j] = fmaf(pv, dsc, mn);
                    }
                }
            }
        }
    }
    __syncwarp();

    // ---- de-stage own channel quarter (scalar LDS -> STG.128) ----
    if (act) {
        float4* og4 = (float4*)(out + (size_t)gch * 196);
        #pragma unroll
        for (int k = 0; k < 13; k++) {
            int i = q + 4 * k;
            if (i < 49)
                og4[i] = make_float4(cb[4*i+0], cb[4*i+1], cb[4*i+2], cb[4*i+3]);
        }
    }
}

extern "C" void kernel_launch(void* const* d_in, const int* in_sizes, int n_in,
                              void* d_out, int out_size)
{
    const float* x = (const float*)d_in[0];
    float* out = (float*)d_out;
    int nch = in_sizes[0] / 196;                 // 32*1024 channels of 14x14
    int chb = WARPS_BLK * 8;                     // 32 channels per block
    int blocks = (nch + chb - 1) / chb;          // 1024
    jpeg_y_kernel<<<blocks, 128>>>(x, out, nch);
}